// round 13
// baseline (speedup 1.0000x reference)
#include <cuda_runtime.h>
#include <cuda_bf16.h>
#include <cstdint>
#include <math.h>

#define NN   50000
#define HID  128
#define EF   800000
#define EP   400000

// ---------------- float scratch layout ----------------
constexpr long F_H    = 0;
constexpr long F_HSF  = F_H    + (long)NN * HID;
constexpr long F_HDF  = F_HSF  + (long)NN * HID;
constexpr long F_HSP  = F_HDF  + (long)NN * HID;
constexpr long F_HDP  = F_HSP  + (long)NN * HID;
constexpr long F_OUTF = F_HDP  + (long)NN * HID;
constexpr long F_OUTP = F_OUTF + (long)NN * HID;
constexpr long F_LOGF = F_OUTP + (long)NN * HID;
constexpr long F_LOGP = F_LOGF + 4L * EF;
constexpr long F_TOT  = F_LOGP + 4L * EP;

// ---------------- int scratch layout -------------------
constexpr long I_DEGF = 0;
constexpr long I_OFFF = I_DEGF + NN;
constexpr long I_CURF = I_OFFF + NN;
constexpr long I_DEGP = I_CURF + NN;
constexpr long I_OFFP = I_DEGP + NN;
constexpr long I_CURP = I_OFFP + NN;
constexpr long I_EIDF = I_CURP + NN;
constexpr long I_EIDP = I_EIDF + (long)EF;
constexpr long I_TOT  = I_EIDP + (long)EP;

__device__ float g_f[F_TOT];
__device__ int   g_i[I_TOT];

// ---------------- helpers ----------------
__device__ __forceinline__ uint32_t f2tf(float x) {
    uint32_t r;
    asm("cvt.rna.tf32.f32 %0, %1;" : "=r"(r) : "f"(x));
    return r;
}

__device__ __forceinline__ void split_tf(float x, uint32_t& hi, uint32_t& lo) {
    hi = f2tf(x);
    float r = x - __uint_as_float(hi);
    lo = f2tf(r);
}

__device__ __forceinline__ void mma8(float* c, const uint32_t* a, const uint32_t* b) {
    asm volatile(
        "mma.sync.aligned.m16n8k8.row.col.f32.tf32.tf32.f32 "
        "{%0,%1,%2,%3}, {%4,%5,%6,%7}, {%8,%9}, {%0,%1,%2,%3};\n"
        : "+f"(c[0]), "+f"(c[1]), "+f"(c[2]), "+f"(c[3])
        : "r"(a[0]), "r"(a[1]), "r"(a[2]), "r"(a[3]),
          "r"(b[0]), "r"(b[1]));
}

__device__ __forceinline__ void cp16(uint32_t dst, const void* src, bool p) {
    int sz = p ? 16 : 0;
    asm volatile("cp.async.ca.shared.global [%0], [%1], 16, %2;\n"
                 :: "r"(dst), "l"(src), "r"(sz));
}

__device__ __forceinline__ uint32_t sptr(const void* p) {
    return (uint32_t)__cvta_generic_to_shared(p);
}

// ============================================================
// GEMM: C[M,128] = A[M,K] @ B[K,128] (+bias), split-TF32
// CTA = 128x128 tile, 8 warps of 32x64, double-buffered cp.async.
// As: [128 rows][stride 20]  (16B-aligned rows, conflict-free frag loads)
// Bs: [16 rows][stride 132]
// ============================================================
__global__ void __launch_bounds__(256) gemm128(
    const float* __restrict__ Aext, long a_off,
    const float* __restrict__ B,
    const float* __restrict__ bias,
    long c_off, int M, int K)
{
    const float* A = Aext ? Aext : (g_f + a_off);
    float* C = g_f + c_off;

    __shared__ float As[2][128 * 20];
    __shared__ float Bs[2][16 * 132];

    int tid  = threadIdx.x;
    int warp = tid >> 5, lane = tid & 31;
    int wm = warp >> 1;        // 0..3
    int wn = warp & 1;         // 0..1
    int m_blk = blockIdx.x * 128;

    float c[2][8][4];
#pragma unroll
    for (int i = 0; i < 2; i++)
#pragma unroll
        for (int j = 0; j < 8; j++)
#pragma unroll
            for (int k = 0; k < 4; k++) c[i][j][k] = 0.f;

    int steps = K >> 4;

    // ---- prologue load ----
    {
        int k0 = 0;
#pragma unroll
        for (int c2 = 0; c2 < 2; c2++) {
            int ch = tid + c2 * 256;
            int row = ch >> 2, j = ch & 3;
            bool ok = (m_blk + row) < M;
            long grow = ok ? (long)(m_blk + row) : 0;
            cp16(sptr(&As[0][row * 20 + j * 4]), A + grow * K + k0 + j * 4, ok);
        }
#pragma unroll
        for (int c2 = 0; c2 < 2; c2++) {
            int ch = tid + c2 * 256;
            int row = ch >> 5, j = ch & 31;
            cp16(sptr(&Bs[0][row * 132 + j * 4]), B + (long)(k0 + row) * 128 + j * 4, true);
        }
        asm volatile("cp.async.commit_group;\n");
    }

    for (int kt = 0; kt < steps; kt++) {
        int b = kt & 1;
        if (kt + 1 < steps) {
            int k0 = (kt + 1) * 16;
            int nb = b ^ 1;
#pragma unroll
            for (int c2 = 0; c2 < 2; c2++) {
                int ch = tid + c2 * 256;
                int row = ch >> 2, j = ch & 3;
                bool ok = (m_blk + row) < M;
                long grow = ok ? (long)(m_blk + row) : 0;
                cp16(sptr(&As[nb][row * 20 + j * 4]), A + grow * K + k0 + j * 4, ok);
            }
#pragma unroll
            for (int c2 = 0; c2 < 2; c2++) {
                int ch = tid + c2 * 256;
                int row = ch >> 5, j = ch & 31;
                cp16(sptr(&Bs[nb][row * 132 + j * 4]), B + (long)(k0 + row) * 128 + j * 4, true);
            }
            asm volatile("cp.async.commit_group;\n");
            asm volatile("cp.async.wait_group 1;\n");
        } else {
            asm volatile("cp.async.wait_group 0;\n");
        }
        __syncthreads();

        // ---- compute on buffer b ----
#pragma unroll
        for (int ks = 0; ks < 2; ks++) {
            int k0 = ks * 8;
            int kk = k0 + (lane & 3);
            uint32_t ah[2][4], al[2][4];
#pragma unroll
            for (int mi = 0; mi < 2; mi++) {
                int r = wm * 32 + mi * 16 + (lane >> 2);
                float a0 = As[b][r * 20 + kk];
                float a1 = As[b][(r + 8) * 20 + kk];
                float a2 = As[b][r * 20 + kk + 4];
                float a3 = As[b][(r + 8) * 20 + kk + 4];
                split_tf(a0, ah[mi][0], al[mi][0]);
                split_tf(a1, ah[mi][1], al[mi][1]);
                split_tf(a2, ah[mi][2], al[mi][2]);
                split_tf(a3, ah[mi][3], al[mi][3]);
            }
#pragma unroll
            for (int ni = 0; ni < 8; ni++) {
                int col = wn * 64 + ni * 8 + (lane >> 2);
                float b0f = Bs[b][kk * 132 + col];
                float b1f = Bs[b][(kk + 4) * 132 + col];
                uint32_t bh[2], bl[2];
                split_tf(b0f, bh[0], bl[0]);
                split_tf(b1f, bh[1], bl[1]);
#pragma unroll
                for (int mi = 0; mi < 2; mi++) {
                    mma8(c[mi][ni], ah[mi], bh);
                    mma8(c[mi][ni], al[mi], bh);
                    mma8(c[mi][ni], ah[mi], bl);
                }
            }
        }
        __syncthreads();
    }

    // ---- epilogue ----
#pragma unroll
    for (int mi = 0; mi < 2; mi++) {
#pragma unroll
        for (int ni = 0; ni < 8; ni++) {
            int col = wn * 64 + ni * 8 + (lane & 3) * 2;
            float bb0 = bias ? bias[col] : 0.f;
            float bb1 = bias ? bias[col + 1] : 0.f;
            int r0 = m_blk + wm * 32 + mi * 16 + (lane >> 2);
            if (r0 < M) {
                float2 v = make_float2(c[mi][ni][0] + bb0, c[mi][ni][1] + bb1);
                *(float2*)(C + (long)r0 * 128 + col) = v;
            }
            int r1 = r0 + 8;
            if (r1 < M) {
                float2 v = make_float2(c[mi][ni][2] + bb0, c[mi][ni][3] + bb1);
                *(float2*)(C + (long)r1 * 128 + col) = v;
            }
        }
    }
}

// ============================================================
// CSR build
// ============================================================
__global__ void zero_ints(long off, int n) {
    int i = blockIdx.x * blockDim.x + threadIdx.x;
    if (i < n) g_i[off + i] = 0;
}

__global__ void count_deg(const int* __restrict__ ei, int E, long deg_off) {
    int e = blockIdx.x * blockDim.x + threadIdx.x;
    if (e < E) atomicAdd(&g_i[deg_off + ei[E + e]], 1);
}

__global__ void scan_deg(long deg_off, long off_off, long cur_off, int n) {
    __shared__ int ssum[1024];
    int t = threadIdx.x;
    int C = (n + 1023) / 1024;
    int lo = t * C, hi = min(n, (t + 1) * C);
    int s = 0;
    for (int i = lo; i < hi; i++) s += g_i[deg_off + i];
    ssum[t] = s;
    __syncthreads();
    for (int d = 1; d < 1024; d <<= 1) {
        int v = (t >= d) ? ssum[t - d] : 0;
        __syncthreads();
        ssum[t] += v;
        __syncthreads();
    }
    int run = (t == 0) ? 0 : ssum[t - 1];
    for (int i = lo; i < hi; i++) {
        g_i[off_off + i] = run;
        g_i[cur_off + i] = run;
        run += g_i[deg_off + i];
    }
}

__global__ void fill_csr(const int* __restrict__ ei, int E, long cur_off, long eid_off) {
    int e = blockIdx.x * blockDim.x + threadIdx.x;
    if (e >= E) return;
    int d = ei[E + e];
    int pos = atomicAdd(&g_i[cur_off + d], 1);
    g_i[eid_off + pos] = e;
}

// ============================================================
// GATv2: one warp per destination node.
// ============================================================
__global__ void __launch_bounds__(256) gat_kernel(
    long hs_off, long hd_off,
    long off_off, long deg_off, long eid_off,
    const int* __restrict__ edge_index,   // [2,E]; row0 = src
    int E,
    const float* __restrict__ edge_w,     // [E]
    const float* __restrict__ wedge,      // [128]
    const float* __restrict__ attn,       // [4,32]
    const float* __restrict__ bias,       // [128]
    long logits_off, long out_off)
{
    const float* hs   = g_f + hs_off;
    const float* hd   = g_f + hd_off;
    const int*   off  = g_i + off_off;
    const int*   degv = g_i + deg_off;
    const int*   eid  = g_i + eid_off;
    float* logits = g_f + logits_off;
    float* out    = g_f + out_off;

    int gw = (blockIdx.x * blockDim.x + threadIdx.x) >> 5;
    if (gw >= NN) return;
    int lane = threadIdx.x & 31;
    int n = gw;
    int begin = off[n];
    int end = begin + degv[n];

    float4 hdv = *(const float4*)(hd + (long)n * 128 + lane * 4);
    float4 wev = *(const float4*)(wedge + lane * 4);
    int h8 = lane >> 3;                          // head this oct handles
    float4 av = *(const float4*)(attn + h8 * 32 + (lane & 7) * 4);

    float maxv = -3.402823466e38f;

    // pass 1: logits + max
    for (int p = begin; p < end; p++) {
        int e = eid[p];
        int s = edge_index[e];
        float w = edge_w[e];
        float4 hsv = *(const float4*)(hs + (long)s * 128 + lane * 4);
        float z0 = hsv.x + hdv.x + w * wev.x; z0 = z0 > 0.f ? z0 : 0.2f * z0;
        float z1 = hsv.y + hdv.y + w * wev.y; z1 = z1 > 0.f ? z1 : 0.2f * z1;
        float z2 = hsv.z + hdv.z + w * wev.z; z2 = z2 > 0.f ? z2 : 0.2f * z2;
        float z3 = hsv.w + hdv.w + w * wev.w; z3 = z3 > 0.f ? z3 : 0.2f * z3;
        float part = av.x * z0 + av.y * z1 + av.z * z2 + av.w * z3;
        part += __shfl_xor_sync(0xffffffffu, part, 4);
        part += __shfl_xor_sync(0xffffffffu, part, 2);
        part += __shfl_xor_sync(0xffffffffu, part, 1);
        if ((lane & 7) == 0) logits[(long)p * 4 + h8] = part;
        maxv = fmaxf(maxv, part);
    }

    float m0 = __shfl_sync(0xffffffffu, maxv, 0);
    float m1 = __shfl_sync(0xffffffffu, maxv, 8);
    float m2 = __shfl_sync(0xffffffffu, maxv, 16);
    float m3 = __shfl_sync(0xffffffffu, maxv, 24);

    // pass 2: sumexp (lane l handles head l&3, positions strided by 8)
    int h4 = lane & 3;
    float mh4 = h4 == 0 ? m0 : h4 == 1 ? m1 : h4 == 2 ? m2 : m3;
    float se = 0.f;
    for (int p = begin + (lane >> 2); p < end; p += 8)
        se += expf(logits[(long)p * 4 + h4] - mh4);
    se += __shfl_xor_sync(0xffffffffu, se, 16);
    se += __shfl_xor_sync(0xffffffffu, se, 8);
    se += __shfl_xor_sync(0xffffffffu, se, 4);
    float s0 = __shfl_sync(0xffffffffu, se, 0);
    float s1 = __shfl_sync(0xffffffffu, se, 1);
    float s2 = __shfl_sync(0xffffffffu, se, 2);
    float s3 = __shfl_sync(0xffffffffu, se, 3);

    float mh8 = h8 == 0 ? m0 : h8 == 1 ? m1 : h8 == 2 ? m2 : m3;
    float sh8 = h8 == 0 ? s0 : h8 == 1 ? s1 : h8 == 2 ? s2 : s3;
    float inv = 1.f / (sh8 + 1e-16f);

    // pass 3: weighted aggregate
    float a0 = 0.f, a1 = 0.f, a2 = 0.f, a3 = 0.f;
    for (int p = begin; p < end; p++) {
        int e = eid[p];
        int s = edge_index[e];
        float lg = logits[(long)p * 4 + h8];
        float att = expf(lg - mh8) * inv;
        float4 hsv = *(const float4*)(hs + (long)s * 128 + lane * 4);
        a0 += att * hsv.x; a1 += att * hsv.y;
        a2 += att * hsv.z; a3 += att * hsv.w;
    }
    float4 o = make_float4(a0 + bias[lane * 4], a1 + bias[lane * 4 + 1],
                           a2 + bias[lane * 4 + 2], a3 + bias[lane * 4 + 3]);
    *(float4*)(out + (long)n * 128 + lane * 4) = o;
}

// ============================================================
// combine + ELU + LayerNorm: one warp per row
// ============================================================
__global__ void __launch_bounds__(256) combine_ln(
    const float* __restrict__ alpha,
    const float* __restrict__ ln_scale,
    const float* __restrict__ ln_bias,
    float* __restrict__ out)
{
    int gw = (blockIdx.x * blockDim.x + threadIdx.x) >> 5;
    if (gw >= NN) return;
    int lane = threadIdx.x & 31;
    float a = *alpha;
    const float* hf = g_f + F_OUTF + (long)gw * 128;
    const float* hp = g_f + F_OUTP + (long)gw * 128;

    float x[4];
#pragma unroll
    for (int i = 0; i < 4; i++) {
        float v = (1.f - a) * hf[lane * 4 + i] + a * hp[lane * 4 + i];
        x[i] = v > 0.f ? v : expm1f(v);
    }
    float s = x[0] + x[1] + x[2] + x[3];
#pragma unroll
    for (int o = 16; o > 0; o >>= 1) s += __shfl_xor_sync(0xffffffffu, s, o);
    float mu = s * (1.f / 128.f);
    float vs = 0.f;
#pragma unroll
    for (int i = 0; i < 4; i++) { float d = x[i] - mu; vs += d * d; }
#pragma unroll
    for (int o = 16; o > 0; o >>= 1) vs += __shfl_xor_sync(0xffffffffu, vs, o);
    float r = rsqrtf(vs * (1.f / 128.f) + 1e-6f);
#pragma unroll
    for (int i = 0; i < 4; i++) {
        int col = lane * 4 + i;
        out[(long)gw * 128 + col] = (x[i] - mu) * r * ln_scale[col] + ln_bias[col];
    }
}

// ============================================================
extern "C" void kernel_launch(void* const* d_in, const int* in_sizes, int n_in,
                              void* d_out, int out_size) {
    const float* X       = (const float*)d_in[0];
    const int*   eif     = (const int*)  d_in[1];
    const float* ewf     = (const float*)d_in[2];
    const int*   eip     = (const int*)  d_in[3];
    const float* ewp     = (const float*)d_in[4];
    const float* alpha   = (const float*)d_in[5];
    const float* ip_w    = (const float*)d_in[6];
    const float* ip_b    = (const float*)d_in[7];
    const float* gf_wsrc = (const float*)d_in[8];
    const float* gf_wdst = (const float*)d_in[9];
    const float* gf_wedge= (const float*)d_in[10];
    const float* gf_attn = (const float*)d_in[11];
    const float* gf_bias = (const float*)d_in[12];
    const float* gp_wsrc = (const float*)d_in[13];
    const float* gp_wdst = (const float*)d_in[14];
    const float* gp_wedge= (const float*)d_in[15];
    const float* gp_attn = (const float*)d_in[16];
    const float* gp_bias = (const float*)d_in[17];
    const float* ln_scale= (const float*)d_in[18];
    const float* ln_bias = (const float*)d_in[19];
    float* out = (float*)d_out;

    int gm = (NN + 127) / 128;   // 391

    // input projection + the 4 h-projections
    gemm128<<<gm, 256>>>(X, 0, ip_w, ip_b, F_H, NN, 2000);
    gemm128<<<gm, 256>>>(nullptr, F_H, gf_wsrc, nullptr, F_HSF, NN, 128);
    gemm128<<<gm, 256>>>(nullptr, F_H, gf_wdst, nullptr, F_HDF, NN, 128);
    gemm128<<<gm, 256>>>(nullptr, F_H, gp_wsrc, nullptr, F_HSP, NN, 128);
    gemm128<<<gm, 256>>>(nullptr, F_H, gp_wdst, nullptr, F_HDP, NN, 128);

    // CSR build (both graphs)
    int gz = (NN + 255) / 256;
    zero_ints<<<gz, 256>>>(I_DEGF, NN);
    zero_ints<<<gz, 256>>>(I_DEGP, NN);
    count_deg<<<(EF + 255) / 256, 256>>>(eif, EF, I_DEGF);
    count_deg<<<(EP + 255) / 256, 256>>>(eip, EP, I_DEGP);
    scan_deg<<<1, 1024>>>(I_DEGF, I_OFFF, I_CURF, NN);
    scan_deg<<<1, 1024>>>(I_DEGP, I_OFFP, I_CURP, NN);
    fill_csr<<<(EF + 255) / 256, 256>>>(eif, EF, I_CURF, I_EIDF);
    fill_csr<<<(EP + 255) / 256, 256>>>(eip, EP, I_CURP, I_EIDP);

    // GATv2 on both graphs
    int gg = (NN * 32 + 255) / 256;
    gat_kernel<<<gg, 256>>>(F_HSF, F_HDF, I_OFFF, I_DEGF, I_EIDF,
                            eif, EF, ewf, gf_wedge, gf_attn, gf_bias,
                            F_LOGF, F_OUTF);
    gat_kernel<<<gg, 256>>>(F_HSP, F_HDP, I_OFFP, I_DEGP, I_EIDP,
                            eip, EP, ewp, gp_wedge, gp_attn, gp_bias,
                            F_LOGP, F_OUTP);

    // combine + elu + layernorm
    combine_ln<<<gg, 256>>>(alpha, ln_scale, ln_bias, out);
}